// round 5
// baseline (speedup 1.0000x reference)
#include <cuda_runtime.h>

// ---------------------------------------------------------------------------
// MaxViT3D MHSA, tf32 tensor-core pipeline (round 5):
//   - operands pre-converted to tf32 bit patterns (GEMM inner loop = LDS+MMA)
//   - conversion kernels reference __device__ globals from DEVICE code only
//     (round-4 bug: passing device symbols as host-side kernel args)
//   - cp.async double-buffered tf32 GEMMs
//   - flash-style attention without online-max, ctx written as tf32 bits
// ---------------------------------------------------------------------------

#define NWIN 128
#define NT   343
#define NTP  352          // padded to 22*16
#define NTB  352          // bias row stride
#define D    256
#define H    8
#define DH   32

// scratch
__device__ float    g_qkv   [(size_t)NWIN * NT * (3 * D)];
__device__ unsigned g_ctx   [(size_t)NWIN * NT * D];        // tf32 bits
__device__ float    g_bias  [(size_t)H * NT * NTB];
__device__ unsigned g_xtf   [(size_t)NWIN * NT * D];        // x as tf32 bits
__device__ unsigned g_wqkvtf[(size_t)D * 3 * D];
__device__ unsigned g_wouttf[(size_t)D * D];

// ---------------------------------------------------------------------------
// helpers
// ---------------------------------------------------------------------------
__device__ __forceinline__ unsigned f2tf(float f) {
    unsigned r;
    asm("cvt.rna.tf32.f32 %0, %1;" : "=r"(r) : "f"(f));
    return r;
}

__device__ __forceinline__ void mma8(float* c, const unsigned* a, const unsigned* b) {
    asm volatile(
        "mma.sync.aligned.m16n8k8.row.col.f32.tf32.tf32.f32 "
        "{%0,%1,%2,%3},{%4,%5,%6,%7},{%8,%9},{%0,%1,%2,%3};"
        : "+f"(c[0]), "+f"(c[1]), "+f"(c[2]), "+f"(c[3])
        : "r"(a[0]), "r"(a[1]), "r"(a[2]), "r"(a[3]), "r"(b[0]), "r"(b[1]));
}

__device__ __forceinline__ unsigned smem_u32(const void* p) {
    unsigned r;
    asm("{.reg .u64 t; cvta.to.shared.u64 t, %1; cvt.u32.u64 %0, t;}"
        : "=r"(r) : "l"(p));
    return r;
}

__device__ __forceinline__ void cpa16(unsigned dst, const void* src) {
    asm volatile("cp.async.ca.shared.global [%0], [%1], 16;" :: "r"(dst), "l"(src));
}
#define CP_COMMIT() asm volatile("cp.async.commit_group;")
#define CP_WAIT0()  asm volatile("cp.async.wait_group 0;")

// ---------------------------------------------------------------------------
// fp32 -> tf32-bits conversion kernels (destinations are device globals,
// referenced from device code only)
// ---------------------------------------------------------------------------
__device__ __forceinline__ void cvt_body(const float4* __restrict__ src,
                                         uint4* __restrict__ dst, int n4) {
    int i = blockIdx.x * blockDim.x + threadIdx.x;
    if (i < n4) {
        float4 v = src[i];
        uint4 o;
        o.x = f2tf(v.x); o.y = f2tf(v.y); o.z = f2tf(v.z); o.w = f2tf(v.w);
        dst[i] = o;
    }
}

__global__ void cvt_x_kernel(const float4* __restrict__ src) {
    cvt_body(src, (uint4*)g_xtf, NWIN * NT * D / 4);
}
__global__ void cvt_wqkv_kernel(const float4* __restrict__ src) {
    cvt_body(src, (uint4*)g_wqkvtf, D * 3 * D / 4);
}
__global__ void cvt_wout_kernel(const float4* __restrict__ src) {
    cvt_body(src, (uint4*)g_wouttf, D * D / 4);
}

// ---------------------------------------------------------------------------
// bias precompute (padded row stride NTB)
// ---------------------------------------------------------------------------
__global__ void bias_kernel(const float* __restrict__ table) {
    int idx = blockIdx.x * blockDim.x + threadIdx.x;
    const int total = H * NT * NTB;
    if (idx >= total) return;
    int h = idx / (NT * NTB);
    int r = idx - h * (NT * NTB);
    int i = r / NTB;
    int j = r - i * NTB;
    float v = 0.0f;
    if (j < NT) {
        int i1 = i / 49, i2 = (i / 7) % 7, i3 = i % 7;
        int j1 = j / 49, j2 = (j / 7) % 7, j3 = j % 7;
        int rel = ((i1 - j1 + 6) * 13 + (i2 - j2 + 6)) * 13 + (i3 - j3 + 6);
        v = table[rel * H + h];
    }
    g_bias[idx] = v;
}

// ---------------------------------------------------------------------------
// tf32 GEMM on pre-converted u32 operands.
// 128x128 block tile, BK=16, 8 warps of 64x32, cp.async 2-stage.
// ---------------------------------------------------------------------------
#define LA 20
#define LB 136

__device__ __forceinline__ void tf32_gemm_body(const unsigned* __restrict__ A,
                                               const unsigned* __restrict__ B,
                                               float* __restrict__ C,
                                               int N, int K) {
    __shared__ unsigned As[2][128 * LA];
    __shared__ unsigned Bs[2][16 * LB];

    const int tid  = threadIdx.x;
    const int warp = tid >> 5, lane = tid & 31;
    const int g = lane >> 2, t = lane & 3;
    const int wm = warp >> 2, wn = warp & 3;

    const int rowBase = blockIdx.y * 128;
    const int colBase = blockIdx.x * 128;

    float acc[4][4][4];
#pragma unroll
    for (int mt = 0; mt < 4; mt++)
#pragma unroll
        for (int nt = 0; nt < 4; nt++)
#pragma unroll
            for (int i = 0; i < 4; i++) acc[mt][nt][i] = 0.0f;

    auto loadTile = [&](int buf, int k0) {
#pragma unroll
        for (int i = 0; i < 2; i++) {
            int c = tid + i * 256;
            int row = c >> 2, q = (c & 3) * 4;
            cpa16(smem_u32(&As[buf][row * LA + q]),
                  A + (size_t)(rowBase + row) * K + k0 + q);
        }
#pragma unroll
        for (int i = 0; i < 2; i++) {
            int c = tid + i * 256;
            int row = c >> 5, col = (c & 31) * 4;
            cpa16(smem_u32(&Bs[buf][row * LB + col]),
                  B + (size_t)(k0 + row) * N + colBase + col);
        }
    };

    loadTile(0, 0);
    CP_COMMIT();

    const int iters = K / 16;
    for (int it = 0; it < iters; it++) {
        CP_WAIT0();
        __syncthreads();
        if (it + 1 < iters) {
            loadTile((it + 1) & 1, (it + 1) * 16);
            CP_COMMIT();
        }
        const unsigned* Ab = As[it & 1];
        const unsigned* Bb = Bs[it & 1];
#pragma unroll
        for (int ks = 0; ks < 16; ks += 8) {
            unsigned a[4][4], b[4][2];
#pragma unroll
            for (int mt = 0; mt < 4; mt++) {
                int r = wm * 64 + mt * 16;
                a[mt][0] = Ab[(r + g)     * LA + ks + t];
                a[mt][1] = Ab[(r + g + 8) * LA + ks + t];
                a[mt][2] = Ab[(r + g)     * LA + ks + t + 4];
                a[mt][3] = Ab[(r + g + 8) * LA + ks + t + 4];
            }
#pragma unroll
            for (int nt = 0; nt < 4; nt++) {
                int cb = wn * 32 + nt * 8;
                b[nt][0] = Bb[(ks + t)     * LB + cb + g];
                b[nt][1] = Bb[(ks + t + 4) * LB + cb + g];
            }
#pragma unroll
            for (int mt = 0; mt < 4; mt++)
#pragma unroll
                for (int nt = 0; nt < 4; nt++) mma8(acc[mt][nt], a[mt], b[nt]);
        }
    }

#pragma unroll
    for (int mt = 0; mt < 4; mt++) {
#pragma unroll
        for (int nt = 0; nt < 4; nt++) {
            int r = rowBase + wm * 64 + mt * 16 + g;
            int c = colBase + wn * 32 + nt * 8 + 2 * t;
            *(float2*)(C + (size_t)r * N + c) =
                make_float2(acc[mt][nt][0], acc[mt][nt][1]);
            *(float2*)(C + (size_t)(r + 8) * N + c) =
                make_float2(acc[mt][nt][2], acc[mt][nt][3]);
        }
    }
}

__global__ __launch_bounds__(256)
void k_gemm_qkv() {
    tf32_gemm_body(g_xtf, g_wqkvtf, g_qkv, 3 * D, D);
}

__global__ __launch_bounds__(256)
void k_gemm_out(float* __restrict__ out) {
    tf32_gemm_body(g_ctx, g_wouttf, out, D, D);
}

// ---------------------------------------------------------------------------
// attention: block = (window, head), 11 warps, 2 q-tiles/warp.
// ---------------------------------------------------------------------------
#define LDKS 36
#define LDVT 356
#define LDP  20
#define AWARPS 11
#define ATHREADS (AWARPS * 32)

__global__ __launch_bounds__(ATHREADS)
void attn_kernel() {
    const int win = blockIdx.x;
    const int h   = blockIdx.y;

    extern __shared__ unsigned sm[];
    unsigned* ks = sm;
    unsigned* vt = ks + NTP * LDKS;
    unsigned* ps = vt + 32 * LDVT;

    const int tid  = threadIdx.x;
    const int warp = tid >> 5, lane = tid & 31;
    const int g = lane >> 2, t = lane & 3;

    const float* base = g_qkv + (size_t)win * NT * (3 * D);

    for (int idx = tid; idx < NTP * DH; idx += ATHREADS) {
        int j = idx >> 5, c = idx & 31;
        float kv = 0.0f, vv = 0.0f;
        if (j < NT) {
            const float* row = base + (size_t)j * (3 * D) + h * DH;
            kv = row[D + c];
            vv = row[2 * D + c];
        }
        ks[j * LDKS + c] = f2tf(kv);
        vt[c * LDVT + j] = f2tf(vv);
    }
    __syncthreads();

    const float scale = 0.17677669529663687f;
    const float* bh = g_bias + (size_t)h * NT * NTB;
    unsigned* pw = ps + warp * 16 * LDP;

    for (int qt = warp; qt < 22; qt += AWARPS) {
        const int i0 = qt * 16;
        const int r1 = i0 + g, r2 = r1 + 8;
        const int r1c = r1 < NT ? r1 : NT - 1;
        const int r2c = r2 < NT ? r2 : NT - 1;

        unsigned qa[4][4];
        const float* qp = base + h * DH;
#pragma unroll
        for (int kq = 0; kq < 4; kq++) {
            qa[kq][0] = f2tf(qp[(size_t)r1c * (3 * D) + kq * 8 + t]);
            qa[kq][1] = f2tf(qp[(size_t)r2c * (3 * D) + kq * 8 + t]);
            qa[kq][2] = f2tf(qp[(size_t)r1c * (3 * D) + kq * 8 + t + 4]);
            qa[kq][3] = f2tf(qp[(size_t)r2c * (3 * D) + kq * 8 + t + 4]);
        }

        float o[4][4];
#pragma unroll
        for (int ct = 0; ct < 4; ct++)
#pragma unroll
            for (int i = 0; i < 4; i++) o[ct][i] = 0.0f;
        float l1 = 0.0f, l2 = 0.0f;

        const float* b1p = bh + (size_t)r1c * NTB;
        const float* b2p = bh + (size_t)r2c * NTB;

        for (int cc = 0; cc < 22; cc++) {
            const int j0 = cc * 16;

            float s0[4] = {0, 0, 0, 0}, s1[4] = {0, 0, 0, 0};
#pragma unroll
            for (int kq = 0; kq < 4; kq++) {
                unsigned b0[2], b1[2];
                b0[0] = ks[(j0 + g)     * LDKS + kq * 8 + t];
                b0[1] = ks[(j0 + g)     * LDKS + kq * 8 + t + 4];
                b1[0] = ks[(j0 + 8 + g) * LDKS + kq * 8 + t];
                b1[1] = ks[(j0 + 8 + g) * LDKS + kq * 8 + t + 4];
                mma8(s0, qa[kq], b0);
                mma8(s1, qa[kq], b1);
            }

            const int c0 = j0 + 2 * t;
            float2 b1a = *(const float2*)(b1p + c0);
            float2 b1b = *(const float2*)(b1p + c0 + 8);
            float2 b2a = *(const float2*)(b2p + c0);
            float2 b2b = *(const float2*)(b2p + c0 + 8);

            float p1[4], p2[4];
            p1[0] = (c0     < NT) ? __expf(fmaf(s0[0], scale, b1a.x)) : 0.0f;
            p1[1] = (c0 + 1 < NT) ? __expf(fmaf(s0[1], scale, b1a.y)) : 0.0f;
            p1[2] = (c0 + 8 < NT) ? __expf(fmaf(s1[0], scale, b1b.x)) : 0.0f;
            p1[3] = (c0 + 9 < NT) ? __expf(fmaf(s1[1], scale, b1b.y)) : 0.0f;
            p2[0] = (c0     < NT) ? __expf(fmaf(s0[2], scale, b2a.x)) : 0.0f;
            p2[1] = (c0 + 1 < NT) ? __expf(fmaf(s0[3], scale, b2a.y)) : 0.0f;
            p2[2] = (c0 + 8 < NT) ? __expf(fmaf(s1[2], scale, b2b.x)) : 0.0f;
            p2[3] = (c0 + 9 < NT) ? __expf(fmaf(s1[3], scale, b2b.y)) : 0.0f;

            l1 += p1[0] + p1[1] + p1[2] + p1[3];
            l2 += p2[0] + p2[1] + p2[2] + p2[3];

            pw[g * LDP + 2 * t]           = f2tf(p1[0]);
            pw[g * LDP + 2 * t + 1]       = f2tf(p1[1]);
            pw[g * LDP + 2 * t + 8]       = f2tf(p1[2]);
            pw[g * LDP + 2 * t + 9]       = f2tf(p1[3]);
            pw[(g + 8) * LDP + 2 * t]     = f2tf(p2[0]);
            pw[(g + 8) * LDP + 2 * t + 1] = f2tf(p2[1]);
            pw[(g + 8) * LDP + 2 * t + 8] = f2tf(p2[2]);
            pw[(g + 8) * LDP + 2 * t + 9] = f2tf(p2[3]);
            __syncwarp();

#pragma unroll
            for (int k2 = 0; k2 < 2; k2++) {
                int kb = k2 * 8;
                unsigned a[4];
                a[0] = pw[g * LDP + kb + t];
                a[1] = pw[(g + 8) * LDP + kb + t];
                a[2] = pw[g * LDP + kb + t + 4];
                a[3] = pw[(g + 8) * LDP + kb + t + 4];
#pragma unroll
                for (int ct = 0; ct < 4; ct++) {
                    unsigned b[2];
                    b[0] = vt[(ct * 8 + g) * LDVT + j0 + kb + t];
                    b[1] = vt[(ct * 8 + g) * LDVT + j0 + kb + t + 4];
                    mma8(o[ct], a, b);
                }
            }
            __syncwarp();
        }

        l1 += __shfl_xor_sync(0xffffffffu, l1, 1);
        l1 += __shfl_xor_sync(0xffffffffu, l1, 2);
        l2 += __shfl_xor_sync(0xffffffffu, l2, 1);
        l2 += __shfl_xor_sync(0xffffffffu, l2, 2);
        const float inv1 = 1.0f / l1;
        const float inv2 = 1.0f / l2;

        // ctx written as tf32 bits (normalized) -> out-proj consumes directly
        if (r1 < NT) {
            unsigned* c1 = g_ctx + ((size_t)win * NT + r1) * D + h * DH;
#pragma unroll
            for (int ct = 0; ct < 4; ct++) {
                c1[ct * 8 + 2 * t]     = f2tf(o[ct][0] * inv1);
                c1[ct * 8 + 2 * t + 1] = f2tf(o[ct][1] * inv1);
            }
        }
        if (r2 < NT) {
            unsigned* c2 = g_ctx + ((size_t)win * NT + r2) * D + h * DH;
#pragma unroll
            for (int ct = 0; ct < 4; ct++) {
                c2[ct * 8 + 2 * t]     = f2tf(o[ct][2] * inv2);
                c2[ct * 8 + 2 * t + 1] = f2tf(o[ct][3] * inv2);
            }
        }
    }
}

// ---------------------------------------------------------------------------
// launch
// ---------------------------------------------------------------------------
extern "C" void kernel_launch(void* const* d_in, const int* in_sizes, int n_in,
                              void* d_out, int out_size) {
    const float* x     = (const float*)d_in[0];
    const float* w_qkv = (const float*)d_in[1];
    const float* w_out = (const float*)d_in[2];
    const float* table = (const float*)d_in[3];
    float* out = (float*)d_out;

    // pre-convert operands to tf32 bits (dst globals referenced device-side)
    {
        int n4x = NWIN * NT * D / 4;
        cvt_x_kernel<<<(n4x + 255) / 256, 256>>>((const float4*)x);
        int n4q = D * 3 * D / 4;
        cvt_wqkv_kernel<<<(n4q + 255) / 256, 256>>>((const float4*)w_qkv);
        int n4o = D * D / 4;
        cvt_wout_kernel<<<(n4o + 255) / 256, 256>>>((const float4*)w_out);
    }
    {
        int total = H * NT * NTB;
        bias_kernel<<<(total + 255) / 256, 256>>>(table);
    }
    {
        dim3 grid(3 * D / 128, (NWIN * NT) / 128);   // (6, 343)
        k_gemm_qkv<<<grid, 256>>>();
    }
    {
        const int smem = (NTP * LDKS + 32 * LDVT + AWARPS * 16 * LDP)
                         * (int)sizeof(unsigned);
        static int configured = -1;
        if (configured < 0) {
            cudaFuncSetAttribute(attn_kernel,
                                 cudaFuncAttributeMaxDynamicSharedMemorySize, smem);
            configured = 1;
        }
        dim3 grid(NWIN, H);
        attn_kernel<<<grid, ATHREADS, smem>>>();
    }
    {
        dim3 grid(D / 128, (NWIN * NT) / 128);       // (2, 343)
        k_gemm_out<<<grid, 256>>>(out);
    }
}